// round 4
// baseline (speedup 1.0000x reference)
#include <cuda_runtime.h>

#define B_   16
#define CIN  32
#define COUT 64
#define H_   16
#define W_   512
#define LRELU_SLOPE 0.3f
#define BN_EPS 1e-5f

typedef unsigned long long u64;

// ---- packed f32x2 helpers ----
__device__ __forceinline__ u64 dup2(float v) {
    u64 r; asm("mov.b64 %0,{%1,%1};" : "=l"(r) : "f"(v)); return r;
}
__device__ __forceinline__ void fma2(u64 &d, u64 a, u64 b) {
    asm("fma.rn.f32x2 %0,%1,%2,%0;" : "+l"(d) : "l"(a), "l"(b));
}
__device__ __forceinline__ void add2(u64 &d, u64 a) {
    asm("add.rn.f32x2 %0,%0,%1;" : "+l"(d) : "l"(a));
}
__device__ __forceinline__ void upk(u64 v, float &lo, float &hi) {
    asm("mov.b64 {%0,%1},%2;" : "=f"(lo), "=f"(hi) : "l"(v));
}

// ---- SMEM layout (float offsets) ----
#define SQ_OFF   0                   // 16x512
#define SK_OFF   8192
#define SV_OFF   16384
#define SPE_OFF  24576
#define SCR_OFF  32768               // 16640 floats: conv staging 32rows x 520 | sS 32x512 | epi tmpA/tmpB
#define SQD_OFF  (SCR_OFF + 16640)   // 49408 : Qdup 16 x 64 (dup'd Q slice)
#define SVN_OFF  (SQD_OFF + 1024)    // 50432 : VnP 32 x 20 (V^T * rinv, h-contiguous)
#define SWOFF    (SVN_OFF + 640)     // 51072 : weights [4t][32ci][12] dup'd+padded
#define SBIAS    (SWOFF + 1536)      // 52608 : 4 biases
#define SSUM     (SBIAS + 4)         // 52612 : 32 rows x 4 warp-partials
#define SMEM_FLOATS (SSUM + 128)     // 52740
#define SMEM_BYTES  (SMEM_FLOATS * 4)// 210960 B

#define XROW 520

__global__ __launch_bounds__(512, 1)
void conv_attn_fused_kernel(
    const float* __restrict__ x,
    const float* __restrict__ wq, const float* __restrict__ gq, const float* __restrict__ bq, const float* __restrict__ mq, const float* __restrict__ vq,
    const float* __restrict__ wk, const float* __restrict__ gk, const float* __restrict__ bk, const float* __restrict__ mk, const float* __restrict__ vk,
    const float* __restrict__ wv, const float* __restrict__ gv, const float* __restrict__ bv, const float* __restrict__ mv, const float* __restrict__ vv,
    const float* __restrict__ wp, const float* __restrict__ gp, const float* __restrict__ bp, const float* __restrict__ mp, const float* __restrict__ vp,
    float* __restrict__ out)
{
    extern __shared__ float sm[];
    const int bid = blockIdx.x;
    const int b   = bid >> 6;
    const int c   = bid & 63;
    const int tid = threadIdx.x;

    // ---------------- BN-folded weights: [t][ci][12], each tap duplicated ----------------
    if (tid < 160) {
        const int ci = tid / 5, kk = tid - ci * 5;
        const int src = c * 160 + ci * 5 + kk;
        const int dst = ci * 12 + 2 * kk;
        float s, a;
        s = gq[c] * rsqrtf(vq[c] + BN_EPS); a = wq[src] * s;
        sm[SWOFF + 0*384 + dst] = a; sm[SWOFF + 0*384 + dst + 1] = a;
        s = gk[c] * rsqrtf(vk[c] + BN_EPS); a = wk[src] * s;
        sm[SWOFF + 1*384 + dst] = a; sm[SWOFF + 1*384 + dst + 1] = a;
        s = gv[c] * rsqrtf(vv[c] + BN_EPS); a = wv[src] * s;
        sm[SWOFF + 2*384 + dst] = a; sm[SWOFF + 2*384 + dst + 1] = a;
        s = gp[c] * rsqrtf(vp[c] + BN_EPS); a = wp[src] * s;
        sm[SWOFF + 3*384 + dst] = a; sm[SWOFF + 3*384 + dst + 1] = a;
    }
    if (tid == 0) {
        float s;
        s = gq[c] * rsqrtf(vq[c] + BN_EPS); sm[SBIAS + 0] = bq[c] - mq[c] * s;
        s = gk[c] * rsqrtf(vk[c] + BN_EPS); sm[SBIAS + 1] = bk[c] - mk[c] * s;
        s = gv[c] * rsqrtf(vv[c] + BN_EPS); sm[SBIAS + 2] = bv[c] - mv[c] * s;
        s = gp[c] * rsqrtf(vp[c] + BN_EPS); sm[SBIAS + 3] = bp[c] - mp[c] * s;
    }
    // zero staging halos (32 rows, idx {2,3,516,517}); staging writes only [4,516)
    if (tid < 128) {
        int row = tid >> 2, q4 = tid & 3;
        int off = (q4 < 2) ? (2 + q4) : (514 + q4);
        sm[SCR_OFF + row * XROW + off] = 0.0f;
    }

    // ---------------- Conv(1x5)+BN+LeakyReLU : 8h x 8w thread tiles, 2 passes ----------------
    const int hgrp = tid >> 6;          // 0..7
    const int w0c  = (tid & 63) << 3;   // 0..504 step 8
    const float* xb = x + (size_t)b * CIN * H_ * W_;

    for (int hb = 0; hb < 2; hb++) {
        u64 acc2[4][4];
        #pragma unroll
        for (int t = 0; t < 4; t++)
            #pragma unroll
            for (int j = 0; j < 4; j++) acc2[t][j] = 0ull;

        for (int cib = 0; cib < 8; cib++) {
            // prefetch stage (4ci x 8h x 512) into regs before barrier
            float4 stg[8];
            #pragma unroll
            for (int it = 0; it < 8; it++) {
                int i  = tid + (it << 9);
                int ci = i >> 10, hh = (i >> 7) & 7, w4 = (i & 127) << 2;
                stg[it] = *(const float4*)&xb[(((size_t)(cib*4 + ci)) * H_ + (hb*8 + hh)) * W_ + w4];
            }
            __syncthreads();
            #pragma unroll
            for (int it = 0; it < 8; it++) {
                int i  = tid + (it << 9);
                int ci = i >> 10, hh = (i >> 7) & 7, w4 = (i & 127) << 2;
                *(float4*)&sm[SCR_OFF + (ci*8 + hh) * XROW + 4 + w4] = stg[it];
            }
            __syncthreads();

            #pragma unroll
            for (int ci4 = 0; ci4 < 4; ci4++) {
                // staged floats xm[m] = x_{w0-4+m}; taps use m = 2..13
                const float* xr = &sm[SCR_OFF + (ci4*8 + hgrp) * XROW + w0c];
                float4 f0 = *(const float4*)(xr);
                float4 f1 = *(const float4*)(xr + 4);
                float4 f2 = *(const float4*)(xr + 8);
                float4 f3 = *(const float4*)(xr + 12);
                float xm[16] = {f0.x,f0.y,f0.z,f0.w, f1.x,f1.y,f1.z,f1.w,
                                f2.x,f2.y,f2.z,f2.w, f3.x,f3.y,f3.z,f3.w};
                u64 P[11];
                #pragma unroll
                for (int n = 0; n < 11; n++) {
                    u64 r; asm("mov.b64 %0,{%1,%2};" : "=l"(r) : "f"(xm[n+2]), "f"(xm[n+3]));
                    P[n] = r;
                }
                const int cig = cib*4 + ci4;
                #pragma unroll
                for (int t = 0; t < 4; t++) {
                    const float* wr = &sm[SWOFF + t*384 + cig*12];
                    ulonglong2 wa = *(const ulonglong2*)wr;        // k0,k1 (dup'd)
                    ulonglong2 wb2 = *(const ulonglong2*)(wr + 4); // k2,k3
                    u64 wc = *(const u64*)(wr + 8);                // k4
                    u64 w5[5] = { wa.x, wa.y, wb2.x, wb2.y, wc };
                    #pragma unroll
                    for (int kk2 = 0; kk2 < 5; kk2++)
                        #pragma unroll
                        for (int jp = 0; jp < 4; jp++)
                            fma2(acc2[t][jp], P[2*jp + kk2], w5[kk2]);
                }
            }
        }
        // write Q/K/V/PE rows
        const int h = hb*8 + hgrp;
        float* dsts[4] = { sm + SQ_OFF, sm + SK_OFF, sm + SV_OFF, sm + SPE_OFF };
        #pragma unroll
        for (int t = 0; t < 4; t++) {
            float bias = sm[SBIAS + t];
            float y[8];
            #pragma unroll
            for (int jp = 0; jp < 4; jp++) {
                float lo, hi; upk(acc2[t][jp], lo, hi);
                y[2*jp]   = lo + bias;
                y[2*jp+1] = hi + bias;
            }
            #pragma unroll
            for (int j = 0; j < 8; j++) y[j] = (y[j] >= 0.f) ? y[j] : LRELU_SLOPE * y[j];
            float* d = &dsts[t][h * W_ + w0c];
            *(float4*)(d)     = make_float4(y[0], y[1], y[2], y[3]);
            *(float4*)(d + 4) = make_float4(y[4], y[5], y[6], y[7]);
        }
    }
    __syncthreads();   // Q/K/V/PE ready

    // ---------------- Attention ----------------
    const int rgrp = tid >> 7;           // 0..3
    const int cb   = (tid & 127) << 2;   // 4 cols
    const int lane = tid & 31, warp = tid >> 5;
    const int wslot = warp & 3;

    u64 oacc[8][4];                      // h-pair packed: 16h x 4c partials (r-split by rgrp)
    #pragma unroll
    for (int i = 0; i < 8; i++)
        #pragma unroll
        for (int j = 0; j < 4; j++) oacc[i][j] = 0ull;

    float* sS = sm + SCR_OFF;

    #pragma unroll 1
    for (int wb = 0; wb < W_; wb += 32) {
        // Qdup slice for this block: Qdup[h][2r{,+1}] = Q[h][wb+r]
        {
            int h2 = tid >> 5;
            float qv = sm[SQ_OFF + h2 * W_ + wb + lane];
            *(float2*)&sm[SQD_OFF + h2 * 64 + 2 * lane] = make_float2(qv, qv);
        }
        __syncthreads();   // sync1: Qdup ready; prior-block consumers all done

        // --- S block: 8r x 4c col-pair packed, operands pre-paired in smem
        u64 sacc[8][2];
        #pragma unroll
        for (int i = 0; i < 8; i++) { sacc[i][0] = 0ull; sacc[i][1] = 0ull; }

        #pragma unroll 4
        for (int h = 0; h < H_; h++) {
            ulonglong2 kk = *(const ulonglong2*)&sm[SK_OFF + h * W_ + cb];
            const float* qd = &sm[SQD_OFF + h * 64 + rgrp * 16];
            #pragma unroll
            for (int j = 0; j < 4; j++) {
                ulonglong2 qq = *(const ulonglong2*)(qd + 4 * j);
                fma2(sacc[2*j  ][0], kk.x, qq.x);
                fma2(sacc[2*j  ][1], kk.y, qq.x);
                fma2(sacc[2*j+1][0], kk.x, qq.y);
                fma2(sacc[2*j+1][1], kk.y, qq.y);
            }
        }

        // --- exp in regs (no max-sub; |S|<~10 << 88), store exp'd S, row partial sums
        float ps[8];
        #pragma unroll
        for (int i = 0; i < 8; i++) {
            float e0, e1, e2, e3;
            upk(sacc[i][0], e0, e1); upk(sacc[i][1], e2, e3);
            e0 = __expf(e0); e1 = __expf(e1); e2 = __expf(e2); e3 = __expf(e3);
            ps[i] = (e0 + e1) + (e2 + e3);
            *(float4*)&sS[(rgrp*8 + i) * W_ + cb] = make_float4(e0, e1, e2, e3);
        }
        #pragma unroll
        for (int i = 0; i < 8; i++)
            #pragma unroll
            for (int o = 16; o; o >>= 1) ps[i] += __shfl_xor_sync(0xffffffffu, ps[i], o);
        if (lane == 0) {
            #pragma unroll
            for (int i = 0; i < 8; i++) sm[SSUM + (rgrp*8 + i) * 4 + wslot] = ps[i];
        }
        __syncthreads();   // sync2: partial sums + exp'd S visible

        // --- VnP[r][h] = V[h][wb+r] * (1/rowsum(r)); h-contiguous natural pairs
        {
            int r = tid & 31, h2 = tid >> 5;   // h2 = 0..15
            float4 p4 = *(const float4*)&sm[SSUM + r * 4];
            float rinv = __fdividef(1.0f, (p4.x + p4.y) + (p4.z + p4.w));
            sm[SVN_OFF + r * 20 + h2] = sm[SV_OFF + h2 * W_ + wb + r] * rinv;
        }
        __syncthreads();   // sync3: VnP ready

        // --- out-update: this rgrp handles r = rgrp*8 .. +8 (A read exactly once)
        #pragma unroll
        for (int j = 0; j < 8; j++) {
            const int r = rgrp*8 + j;
            float4 a4 = *(const float4*)&sS[r * W_ + cb];
            const float* vr = &sm[SVN_OFF + r * 20];
            ulonglong2 v0 = *(const ulonglong2*)(vr);
            ulonglong2 v1 = *(const ulonglong2*)(vr + 4);
            ulonglong2 v2 = *(const ulonglong2*)(vr + 8);
            ulonglong2 v3 = *(const ulonglong2*)(vr + 12);
            u64 vp[8] = { v0.x, v0.y, v1.x, v1.y, v2.x, v2.y, v3.x, v3.y };
            u64 da[4] = { dup2(a4.x), dup2(a4.y), dup2(a4.z), dup2(a4.w) };
            #pragma unroll
            for (int hp = 0; hp < 8; hp++)
                #pragma unroll
                for (int cc = 0; cc < 4; cc++)
                    fma2(oacc[hp][cc], vp[hp], da[cc]);
        }
        // next block's sync1 orders these reads before sS/VnP overwrite
    }
    __syncthreads();   // out-updates done before epilogue reuses scratch

    // ---------------- Epilogue: combine 4 r-split partials, add PE, store ----------------
    float* tmpA = sm + SCR_OFF;          // 8192 floats: [hp][c][2]
    float* tmpB = sm + SCR_OFF + 8192;
    if (rgrp == 0) {
        #pragma unroll
        for (int hp = 0; hp < 8; hp++)
            #pragma unroll
            for (int cc = 0; cc < 4; cc++)
                *(u64*)&tmpA[hp*1024 + (cb + cc)*2] = oacc[hp][cc];
    } else if (rgrp == 1) {
        #pragma unroll
        for (int hp = 0; hp < 8; hp++)
            #pragma unroll
            for (int cc = 0; cc < 4; cc++)
                *(u64*)&tmpB[hp*1024 + (cb + cc)*2] = oacc[hp][cc];
    }
    __syncthreads();
    if (rgrp == 2) {
        #pragma unroll
        for (int hp = 0; hp < 8; hp++)
            #pragma unroll
            for (int cc = 0; cc < 4; cc++) {
                u64* p = (u64*)&tmpA[hp*1024 + (cb + cc)*2];
                u64 v = *p; add2(v, oacc[hp][cc]); *p = v;
            }
    } else if (rgrp == 3) {
        #pragma unroll
        for (int hp = 0; hp < 8; hp++)
            #pragma unroll
            for (int cc = 0; cc < 4; cc++) {
                u64* p = (u64*)&tmpB[hp*1024 + (cb + cc)*2];
                u64 v = *p; add2(v, oacc[hp][cc]); *p = v;
            }
    }
    __syncthreads();

    float* og = out + (size_t)bid * (H_ * W_);
    #pragma unroll
    for (int it = 0; it < 4; it++) {
        int fi = (tid + it*512) * 4;       // flat float index into 16x512 output
        int h  = fi >> 9;
        int w  = fi & 511;
        int t0 = (h >> 1) * 1024 + w * 2 + (h & 1);
        float o0 = tmpA[t0]     + tmpB[t0];
        float o1 = tmpA[t0 + 2] + tmpB[t0 + 2];
        float o2 = tmpA[t0 + 4] + tmpB[t0 + 4];
        float o3 = tmpA[t0 + 6] + tmpB[t0 + 6];
        float4 pe = *(const float4*)&sm[SPE_OFF + h * W_ + w];
        *(float4*)&og[h * W_ + w] =
            make_float4(o0 + pe.x, o1 + pe.y, o2 + pe.z, o3 + pe.w);
    }
}

extern "C" void kernel_launch(void* const* d_in, const int* in_sizes, int n_in,
                              void* d_out, int out_size)
{
    cudaFuncSetAttribute(conv_attn_fused_kernel,
                         cudaFuncAttributeMaxDynamicSharedMemorySize, SMEM_BYTES);

    const float* x  = (const float*)d_in[0];
    const float* wq = (const float*)d_in[1];
    const float* gq = (const float*)d_in[2];
    const float* bq = (const float*)d_in[3];
    const float* mq = (const float*)d_in[4];
    const float* vq = (const float*)d_in[5];
    const float* wk = (const float*)d_in[6];
    const float* gk = (const float*)d_in[7];
    const float* bk = (const float*)d_in[8];
    const float* mk = (const float*)d_in[9];
    const float* vk = (const float*)d_in[10];
    const float* wv = (const float*)d_in[11];
    const float* gv = (const float*)d_in[12];
    const float* bv = (const float*)d_in[13];
    const float* mv = (const float*)d_in[14];
    const float* vv = (const float*)d_in[15];
    const float* wp = (const float*)d_in[16];
    const float* gp = (const float*)d_in[17];
    const float* bp = (const float*)d_in[18];
    const float* mp = (const float*)d_in[19];
    const float* vp = (const float*)d_in[20];

    conv_attn_fused_kernel<<<B_ * COUT, 512, SMEM_BYTES>>>(
        x,
        wq, gq, bq, mq, vq,
        wk, gk, bk, mk, vk,
        wv, gv, bv, mv, vv,
        wp, gp, bp, mp, vp,
        (float*)d_out);
}